// round 1
// baseline (speedup 1.0000x reference)
#include <cuda_runtime.h>

// DenseGrid trilinear interpolation
// inputs: xyz (N,3) f32, grid (1,12,160,160,160) f32, xyz_min (3) f32, xyz_max (3) f32
// output: out (N,12) f32

constexpr int C  = 12;
constexpr int Dz = 160;
constexpr int Hy = 160;
constexpr int Wx = 160;
constexpr int HW  = Hy * Wx;        // 25600
constexpr int DHW = Dz * HW;        // 4096000

__global__ __launch_bounds__(256)
void trilerp_kernel(const float* __restrict__ xyz,
                    const float* __restrict__ grid,
                    const float* __restrict__ xyz_min,
                    const float* __restrict__ xyz_max,
                    float* __restrict__ out,
                    int n)
{
    int i = blockIdx.x * blockDim.x + threadIdx.x;
    if (i >= n) return;

    // read point (coalesced across warp: contiguous floats)
    float px = xyz[3 * i + 0];
    float py = xyz[3 * i + 1];
    float pz = xyz[3 * i + 2];

    // bounds (broadcast loads, L1-resident)
    float mn0 = __ldg(&xyz_min[0]), mn1 = __ldg(&xyz_min[1]), mn2 = __ldg(&xyz_min[2]);
    float mx0 = __ldg(&xyz_max[0]), mx1 = __ldg(&xyz_max[1]), mx2 = __ldg(&xyz_max[2]);

    // u = (p - min)/(max - min) * (size-1), clamped to [0, size-1]
    float ud = (px - mn0) / (mx0 - mn0) * (float)(Dz - 1);
    float uh = (py - mn1) / (mx1 - mn1) * (float)(Hy - 1);
    float uw = (pz - mn2) / (mx2 - mn2) * (float)(Wx - 1);
    ud = fminf(fmaxf(ud, 0.0f), (float)(Dz - 1));
    uh = fminf(fmaxf(uh, 0.0f), (float)(Hy - 1));
    uw = fminf(fmaxf(uw, 0.0f), (float)(Wx - 1));

    // i0 = clamp(floor(u), 0, size-2); f = u - i0
    float fd0 = fminf(floorf(ud), (float)(Dz - 2));
    float fh0 = fminf(floorf(uh), (float)(Hy - 2));
    float fw0 = fminf(floorf(uw), (float)(Wx - 2));
    float fd = ud - fd0;
    float fh = uh - fh0;
    float fw = uw - fw0;

    int d0 = (int)fd0;
    int h0 = (int)fh0;
    int w0 = (int)fw0;

    // 8 corner weights
    float cd0 = 1.0f - fd, ch0 = 1.0f - fh, cw0 = 1.0f - fw;
    float w000 = cd0 * ch0 * cw0;
    float w001 = cd0 * ch0 * fw;
    float w010 = cd0 * fh  * cw0;
    float w011 = cd0 * fh  * fw;
    float w100 = fd  * ch0 * cw0;
    float w101 = fd  * ch0 * fw;
    float w110 = fd  * fh  * cw0;
    float w111 = fd  * fh  * fw;

    long base = (long)d0 * HW + (long)h0 * Wx + w0;
    const float* __restrict__ g = grid + base;

    float* __restrict__ o = out + (long)i * C;

    // 12 channels, 8 gathers each. Full unroll -> deep MLP.
    #pragma unroll
    for (int c = 0; c < C; ++c) {
        const float* gc = g + (long)c * DHW;
        float v000 = __ldg(gc + 0);
        float v001 = __ldg(gc + 1);
        float v010 = __ldg(gc + Wx);
        float v011 = __ldg(gc + Wx + 1);
        float v100 = __ldg(gc + HW);
        float v101 = __ldg(gc + HW + 1);
        float v110 = __ldg(gc + HW + Wx);
        float v111 = __ldg(gc + HW + Wx + 1);
        float v = v000 * w000 + v001 * w001 + v010 * w010 + v011 * w011
                + v100 * w100 + v101 * w101 + v110 * w110 + v111 * w111;
        o[c] = v;
    }
}

extern "C" void kernel_launch(void* const* d_in, const int* in_sizes, int n_in,
                              void* d_out, int out_size)
{
    const float* xyz     = (const float*)d_in[0];
    const float* grid    = (const float*)d_in[1];
    const float* xyz_min = (const float*)d_in[2];
    const float* xyz_max = (const float*)d_in[3];
    float* out = (float*)d_out;

    int n = in_sizes[0] / 3;   // N points
    int threads = 256;
    int blocks = (n + threads - 1) / threads;
    trilerp_kernel<<<blocks, threads>>>(xyz, grid, xyz_min, xyz_max, out, n);
}

// round 2
// speedup vs baseline: 4.9442x; 4.9442x over previous
#include <cuda_runtime.h>
#include <cuda_fp16.h>

// DenseGrid trilinear interpolation, two-pass:
//   1) repack grid (1,C,D,H,W) fp32 -> channels-last fp16, 32B/voxel (padded)
//   2) gather: each corner = one aligned 32B sector (2x LDG.128)

constexpr int C  = 12;
constexpr int Dz = 160;
constexpr int Hy = 160;
constexpr int Wx = 160;
constexpr int HW   = Hy * Wx;       // 25600
constexpr int DHW  = Dz * HW;       // 4096000
constexpr int NVOX = DHW;
constexpr int VS   = 16;            // halves per voxel (12 data + 4 pad) = 32B

// 131 MB static scratch (allowed: __device__ global array)
__device__ __align__(32) __half g_scratch[(size_t)NVOX * VS];

__global__ __launch_bounds__(256)
void repack_kernel(const float* __restrict__ grid)
{
    int v = blockIdx.x * blockDim.x + threadIdx.x;
    if (v >= NVOX) return;

    __half h[VS];
    #pragma unroll
    for (int c = 0; c < C; ++c)
        h[c] = __float2half(grid[(size_t)c * DHW + v]);
    #pragma unroll
    for (int c = C; c < VS; ++c)
        h[c] = __float2half(0.0f);

    uint4* dst = reinterpret_cast<uint4*>(g_scratch + (size_t)v * VS);
    dst[0] = *reinterpret_cast<uint4*>(&h[0]);
    dst[1] = *reinterpret_cast<uint4*>(&h[8]);
}

__global__ __launch_bounds__(256)
void gather_kernel(const float* __restrict__ xyz,
                   const float* __restrict__ xyz_min,
                   const float* __restrict__ xyz_max,
                   float* __restrict__ out,
                   int n)
{
    int i = blockIdx.x * blockDim.x + threadIdx.x;
    if (i >= n) return;

    float px = xyz[3 * i + 0];
    float py = xyz[3 * i + 1];
    float pz = xyz[3 * i + 2];

    float mn0 = __ldg(&xyz_min[0]), mn1 = __ldg(&xyz_min[1]), mn2 = __ldg(&xyz_min[2]);
    float mx0 = __ldg(&xyz_max[0]), mx1 = __ldg(&xyz_max[1]), mx2 = __ldg(&xyz_max[2]);

    float ud = (px - mn0) / (mx0 - mn0) * (float)(Dz - 1);
    float uh = (py - mn1) / (mx1 - mn1) * (float)(Hy - 1);
    float uw = (pz - mn2) / (mx2 - mn2) * (float)(Wx - 1);
    ud = fminf(fmaxf(ud, 0.0f), (float)(Dz - 1));
    uh = fminf(fmaxf(uh, 0.0f), (float)(Hy - 1));
    uw = fminf(fmaxf(uw, 0.0f), (float)(Wx - 1));

    float fd0 = fminf(floorf(ud), (float)(Dz - 2));
    float fh0 = fminf(floorf(uh), (float)(Hy - 2));
    float fw0 = fminf(floorf(uw), (float)(Wx - 2));
    float fd = ud - fd0;
    float fh = uh - fh0;
    float fw = uw - fw0;

    int d0 = (int)fd0;
    int h0 = (int)fh0;
    int w0 = (int)fw0;

    float cd0 = 1.0f - fd, ch0 = 1.0f - fh, cw0 = 1.0f - fw;
    float wgt[8];
    wgt[0] = cd0 * ch0 * cw0;  // d0 h0 w0
    wgt[1] = cd0 * ch0 * fw;   // d0 h0 w1
    wgt[2] = cd0 * fh  * cw0;  // d0 h1 w0
    wgt[3] = cd0 * fh  * fw;   // d0 h1 w1
    wgt[4] = fd  * ch0 * cw0;  // d1 h0 w0
    wgt[5] = fd  * ch0 * fw;   // d1 h0 w1
    wgt[6] = fd  * fh  * cw0;  // d1 h1 w0
    wgt[7] = fd  * fh  * fw;   // d1 h1 w1

    int base = ((d0 * Hy + h0) * Wx + w0) * VS;   // fits in int (max ~65.5M)
    const int offs[8] = {
        0,                VS,
        Wx * VS,          Wx * VS + VS,
        HW * VS,          HW * VS + VS,
        (HW + Wx) * VS,   (HW + Wx) * VS + VS
    };

    float acc[C];
    #pragma unroll
    for (int c = 0; c < C; ++c) acc[c] = 0.0f;

    #pragma unroll
    for (int k = 0; k < 8; ++k) {
        const uint4* p = reinterpret_cast<const uint4*>(g_scratch + base + offs[k]);
        uint4 a = __ldg(p);       // ch 0..7
        uint4 b = __ldg(p + 1);   // ch 8..11 in .x/.y
        float w = wgt[k];

        float2 f;
        f = __half22float2(*reinterpret_cast<__half2*>(&a.x));
        acc[0]  += w * f.x;  acc[1]  += w * f.y;
        f = __half22float2(*reinterpret_cast<__half2*>(&a.y));
        acc[2]  += w * f.x;  acc[3]  += w * f.y;
        f = __half22float2(*reinterpret_cast<__half2*>(&a.z));
        acc[4]  += w * f.x;  acc[5]  += w * f.y;
        f = __half22float2(*reinterpret_cast<__half2*>(&a.w));
        acc[6]  += w * f.x;  acc[7]  += w * f.y;
        f = __half22float2(*reinterpret_cast<__half2*>(&b.x));
        acc[8]  += w * f.x;  acc[9]  += w * f.y;
        f = __half22float2(*reinterpret_cast<__half2*>(&b.y));
        acc[10] += w * f.x;  acc[11] += w * f.y;
    }

    // 48B contiguous per thread; consecutive threads contiguous -> fully used sectors
    float4* o = reinterpret_cast<float4*>(out + (size_t)i * C);
    o[0] = make_float4(acc[0], acc[1], acc[2],  acc[3]);
    o[1] = make_float4(acc[4], acc[5], acc[6],  acc[7]);
    o[2] = make_float4(acc[8], acc[9], acc[10], acc[11]);
}

extern "C" void kernel_launch(void* const* d_in, const int* in_sizes, int n_in,
                              void* d_out, int out_size)
{
    const float* xyz     = (const float*)d_in[0];
    const float* grid    = (const float*)d_in[1];
    const float* xyz_min = (const float*)d_in[2];
    const float* xyz_max = (const float*)d_in[3];
    float* out = (float*)d_out;

    int n = in_sizes[0] / 3;

    int rthreads = 256;
    int rblocks  = (NVOX + rthreads - 1) / rthreads;
    repack_kernel<<<rblocks, rthreads>>>(grid);

    int gthreads = 256;
    int gblocks  = (n + gthreads - 1) / gthreads;
    gather_kernel<<<gblocks, gthreads>>>(xyz, xyz_min, xyz_max, out, n);
}